// round 7
// baseline (speedup 1.0000x reference)
#include <cuda_runtime.h>
#include <cuda_bf16.h>

// BSplineKAN, uniform knots linspace(-1,1,12), order 3, h = 2/11.
//
// Per (channel, knot-interval) the output collapses to ONE cubic in local
// coordinate t (uniform cubic B-spline matrix). Each block builds the coeff
// table in a register prologue, then the hot loop is
//   clamp -> magic-floor j,t -> conflict-free LDS.128 -> Estrin cubic.
//
// Magic floor (FIXED from round 5): bias into the MIDDLE of the exponent-23
// binade so the value never leaves it:
//   base = 1.5*2^23 = 12582912,  m = fma(xx, 5.5, base + 5.0)
//        = base + (u - 0.5) in [base-0.445, base+10.445]  (ulp = 1 throughout)
//   => m = base + floor(u) after round-to-nearest (ties at knots are
//      harmless by C^2 continuity). Mantissa(base+k) = 2^22 + k, so
//   j  = __float_as_int(m) & 15   (k in 0..10)
//   t  = u - (m - base)
// Round-5's base of 2^23 itself dipped into the exp-22 binade for u<0.5,
// producing j=15 and an OOB shared read. Table is now sized 16x64 (zero
// filled past j=10) so ANY j in 0..15 is in-bounds by construction.
//
// Swizzle: lane l's channels are 4*(l&15)+s. Slot (((c&3)<<4)|(c>>2)) makes
// each 8-lane LDS.128 phase tile all 32 banks for any data-dependent j.

#define NUM_CH 64
#define NUM_CP 8
#define NUM_INTERVALS 11
#define TAB_J 16                      // padded interval count (power of two)
#define FBASE 12582912.0f             // 1.5 * 2^23

__global__ __launch_bounds__(256)
void kan_fused_kernel(const float4* __restrict__ x4,
                      const float* __restrict__ cp,
                      float4* __restrict__ out4, int nvec) {
    __shared__ float4 sco[TAB_J * NUM_CH];           // 16 KB, swizzled

    // ---- prologue: t-polynomial coeff table (uniform B-spline matrix /6) ----
    const float M[4][4] = {
        { 1.f/6.f, -3.f/6.f,  3.f/6.f, -1.f/6.f },
        { 4.f/6.f,  0.f,     -6.f/6.f,  3.f/6.f },
        { 1.f/6.f,  3.f/6.f,  3.f/6.f, -3.f/6.f },
        { 0.f,      0.f,      0.f,      1.f/6.f },
    };
    for (int idx = threadIdx.x; idx < TAB_J * NUM_CH; idx += blockDim.x) {
        const int j = idx >> 6;          // 0..15
        const int c = idx & 63;
        float a0 = 0.f, a1 = 0.f, a2 = 0.f, a3 = 0.f;
        if (j < NUM_INTERVALS) {
#pragma unroll
            for (int k = 0; k < 4; k++) {
                const int i = j - 3 + k;
                if (i >= 0 && i < NUM_CP) {
                    const float p = __ldg(&cp[c * NUM_CP + i]);
                    a0 = fmaf(p, M[k][0], a0);
                    a1 = fmaf(p, M[k][1], a1);
                    a2 = fmaf(p, M[k][2], a2);
                    a3 = fmaf(p, M[k][3], a3);
                }
            }
        }
        const int slot = ((c & 3) << 4) | (c >> 2);   // bank-tiling swizzle
        sco[(j << 6) + slot] = make_float4(a0, a1, a2, a3);
    }
    __syncthreads();

    // ---- hot loop: 2 float4s per thread per iteration ----
    const int cbase = (threadIdx.x << 2) & 63;
    int slot_s[4];
#pragma unroll
    for (int s = 0; s < 4; s++) {
        const int c = cbase + s;
        slot_s[s] = ((c & 3) << 4) | (c >> 2);
    }

    const int chunk  = 2 * blockDim.x;                // 512 float4s per block-iter
    const int stride = gridDim.x * chunk;

    for (int base = blockIdx.x * chunk + threadIdx.x; base < nvec; base += stride) {
        const int v0 = base;
        const int v1 = base + (int)blockDim.x;
        const bool has1 = (v1 < nvec);

        float4 xa = x4[v0];
        float4 xb = has1 ? x4[v1] : make_float4(0.f, 0.f, 0.f, 0.f);

        float xin[8] = {xa.x, xa.y, xa.z, xa.w, xb.x, xb.y, xb.z, xb.w};
        float yo[8];
#pragma unroll
        for (int s = 0; s < 8; s++) {
            float xx = fminf(fmaxf(xin[s], -0.99f), 0.99f);
            // u = (xx+1)*5.5 in [0.055, 10.945]
            float u  = fmaf(xx, 5.5f, 5.5f);
            // magic floor: m = FBASE + floor(u), ulp=1 across whole range
            float m  = fmaf(xx, 5.5f, FBASE + 5.0f);
            int   j  = __float_as_int(m) & 15;        // = floor(u), 0..10
            float t  = u - (m - FBASE);
            const float4 co = sco[(j << 6) + slot_s[s & 3]];
            // Estrin: (a0 + a1 t) + t^2 (a2 + a3 t)
            float t2 = t * t;
            float lo = fmaf(co.y, t, co.x);
            float hi = fmaf(co.w, t, co.z);
            yo[s] = fmaf(hi, t2, lo);
        }
        out4[v0] = make_float4(yo[0], yo[1], yo[2], yo[3]);
        if (has1)
            out4[v1] = make_float4(yo[4], yo[5], yo[6], yo[7]);
    }
}

extern "C" void kernel_launch(void* const* d_in, const int* in_sizes, int n_in,
                              void* d_out, int out_size) {
    const float* x  = (const float*)d_in[0];          // [262144, 64]
    const float* cp = (const float*)d_in[1];          // [64, 8]
    float* out = (float*)d_out;

    const int n = in_sizes[0];                        // B*C elements
    const int nvec = n >> 2;                          // float4 count

    const int threads = 256;
    const int blocks = 1184;                          // 148 SMs x 8 CTAs
    kan_fused_kernel<<<blocks, threads>>>((const float4*)x, cp,
                                          (float4*)out, nvec);
}

// round 8
// speedup vs baseline: 1.6228x; 1.6228x over previous
#include <cuda_runtime.h>
#include <cuda_bf16.h>

// BSplineKAN, uniform knots linspace(-1,1,12), order 3, h = 2/11.
//
// Per (channel, knot-interval) the output collapses to ONE cubic in local
// coordinate t (uniform cubic B-spline matrix). Each block builds the coeff
// table in a register prologue, then the hot loop is
//   clamp -> magic-floor j,t -> conflict-free LDS.128 -> Estrin cubic.
//
// Magic floor: bias into the middle of the exponent-23 binade:
//   base = 1.5*2^23 = 12582912,  m = fma(xx, 5.5, base + 5.0)
//        = base + (u - 0.5) in [base-0.445, base+10.445], ulp = 1 throughout
//   => m = base + floor(u); mantissa(base+k) = 2^22 + k, so
//   j = __float_as_int(m) & 15  (0..10),  t = u - (m - base).
// Round-7 lesson: padding the table to 16 rows (16 KB smem) cut occupancy
// 88% -> 57% (smem budget fits only 5 CTAs/SM) and DOUBLED runtime. Safety
// is now one IMNMX (min(j,10)) instead of 5 KB of padding; table back to
// 11 rows = 11,264 B -> 8 CTAs/SM.
//
// Swizzle: lane l's channels are 4*(l&15)+s. Slot (((c&3)<<4)|(c>>2)) makes
// each 8-lane LDS.128 phase tile all 32 banks for any data-dependent j.

#define NUM_CH 64
#define NUM_CP 8
#define NUM_INTERVALS 11
#define FBASE 12582912.0f             // 1.5 * 2^23

__global__ __launch_bounds__(256)
void kan_fused_kernel(const float4* __restrict__ x4,
                      const float* __restrict__ cp,
                      float4* __restrict__ out4, int nvec) {
    __shared__ float4 sco[NUM_INTERVALS * NUM_CH];   // 11,264 B, swizzled

    // ---- prologue: t-polynomial coeff table (uniform B-spline matrix /6) ----
    const float M[4][4] = {
        { 1.f/6.f, -3.f/6.f,  3.f/6.f, -1.f/6.f },
        { 4.f/6.f,  0.f,     -6.f/6.f,  3.f/6.f },
        { 1.f/6.f,  3.f/6.f,  3.f/6.f, -3.f/6.f },
        { 0.f,      0.f,      0.f,      1.f/6.f },
    };
    for (int idx = threadIdx.x; idx < NUM_INTERVALS * NUM_CH; idx += blockDim.x) {
        const int j = idx >> 6;          // 0..10
        const int c = idx & 63;
        float a0 = 0.f, a1 = 0.f, a2 = 0.f, a3 = 0.f;
#pragma unroll
        for (int k = 0; k < 4; k++) {
            const int i = j - 3 + k;
            if (i >= 0 && i < NUM_CP) {
                const float p = __ldg(&cp[c * NUM_CP + i]);
                a0 = fmaf(p, M[k][0], a0);
                a1 = fmaf(p, M[k][1], a1);
                a2 = fmaf(p, M[k][2], a2);
                a3 = fmaf(p, M[k][3], a3);
            }
        }
        const int slot = ((c & 3) << 4) | (c >> 2);   // bank-tiling swizzle
        sco[(j << 6) + slot] = make_float4(a0, a1, a2, a3);
    }
    __syncthreads();

    // ---- hot loop: 2 float4s per thread per iteration ----
    const int cbase = (threadIdx.x << 2) & 63;
    int slot_s[4];
#pragma unroll
    for (int s = 0; s < 4; s++) {
        const int c = cbase + s;
        slot_s[s] = ((c & 3) << 4) | (c >> 2);
    }

    const int chunk  = 2 * blockDim.x;                // 512 float4s per block-iter
    const int stride = gridDim.x * chunk;

    for (int base = blockIdx.x * chunk + threadIdx.x; base < nvec; base += stride) {
        const int v0 = base;
        const int v1 = base + (int)blockDim.x;
        const bool has1 = (v1 < nvec);

        float4 xa = x4[v0];
        float4 xb = has1 ? x4[v1] : make_float4(0.f, 0.f, 0.f, 0.f);

        float xin[8] = {xa.x, xa.y, xa.z, xa.w, xb.x, xb.y, xb.z, xb.w};
        float yo[8];
#pragma unroll
        for (int s = 0; s < 8; s++) {
            float xx = fminf(fmaxf(xin[s], -0.99f), 0.99f);
            // u = (xx+1)*5.5 in [0.055, 10.945]
            float u  = fmaf(xx, 5.5f, 5.5f);
            // magic floor: m = FBASE + floor(u), ulp=1 across whole range
            float m  = fmaf(xx, 5.5f, FBASE + 5.0f);
            int   j  = __float_as_int(m) & 15;        // = floor(u), 0..10
            j = min(j, NUM_INTERVALS - 1);            // 1-op fault insurance
            float t  = u - (m - FBASE);
            const float4 co = sco[(j << 6) + slot_s[s & 3]];
            // Estrin: (a0 + a1 t) + t^2 (a2 + a3 t)
            float t2 = t * t;
            float lo = fmaf(co.y, t, co.x);
            float hi = fmaf(co.w, t, co.z);
            yo[s] = fmaf(hi, t2, lo);
        }
        out4[v0] = make_float4(yo[0], yo[1], yo[2], yo[3]);
        if (has1)
            out4[v1] = make_float4(yo[4], yo[5], yo[6], yo[7]);
    }
}

extern "C" void kernel_launch(void* const* d_in, const int* in_sizes, int n_in,
                              void* d_out, int out_size) {
    const float* x  = (const float*)d_in[0];          // [262144, 64]
    const float* cp = (const float*)d_in[1];          // [64, 8]
    float* out = (float*)d_out;

    const int n = in_sizes[0];                        // B*C elements
    const int nvec = n >> 2;                          // float4 count

    const int threads = 256;
    const int blocks = 1184;                          // 148 SMs x 8 CTAs
    kan_fused_kernel<<<blocks, threads>>>((const float4*)x, cp,
                                          (float4*)out, nvec);
}

// round 9
// speedup vs baseline: 1.7449x; 1.0753x over previous
#include <cuda_runtime.h>
#include <cuda_bf16.h>

// BSplineKAN, uniform knots linspace(-1,1,12), order 3, h = 2/11.
//
// Per (channel, knot-interval) the output collapses to ONE cubic in local
// coordinate t (uniform cubic B-spline matrix). Each block builds the coeff
// table in a register prologue; hot loop:
//   clamp -> magic-floor j,t -> conflict-free LDS.128 -> 3-FMA Horner.
//
// Magic floor: base = 1.5*2^23; m = fma(xx,5.5, base+5.0) = base + floor(u)
// (u in [0.055,10.945], whole range in the ulp=1 binade). j = bits(m)&15
// is PROVEN in [0,10]; NaN inputs collapse to -0.99 at the clamp.
//
// R9 rationale: regs are pinned at 32 (8 CTAs x 256 thr x 32 = full RF) and
// R7 showed occupancy loss is catastrophic, so optimize issue slots at fixed
// occupancy: Horner (3 FMA) over Estrin (4 ops), drop the j-clamp IMNMX,
// 2-op addressing (LOP + IMAD(j,1024,per-s byte base)). Streaming stores
// (__stcs) mark output evict-first so x (67 MB) stays L2-resident
// (x+out = 134 MB was thrashing the 126 MB L2), cutting LDG latency.
//
// Swizzle: lane l's channels are 4*(l&15)+s. Slot (((c&3)<<4)|(c>>2)) makes
// each 8-lane LDS.128 phase tile all 32 banks for any data-dependent j.

#define NUM_CH 64
#define NUM_CP 8
#define NUM_INTERVALS 11
#define FBASE 12582912.0f             // 1.5 * 2^23

__global__ __launch_bounds__(256)
void kan_fused_kernel(const float4* __restrict__ x4,
                      const float* __restrict__ cp,
                      float4* __restrict__ out4, int nvec) {
    __shared__ float4 sco[NUM_INTERVALS * NUM_CH];   // 11,264 B, swizzled

    // ---- prologue: t-polynomial coeff table (uniform B-spline matrix /6) ----
    const float M[4][4] = {
        { 1.f/6.f, -3.f/6.f,  3.f/6.f, -1.f/6.f },
        { 4.f/6.f,  0.f,     -6.f/6.f,  3.f/6.f },
        { 1.f/6.f,  3.f/6.f,  3.f/6.f, -3.f/6.f },
        { 0.f,      0.f,      0.f,      1.f/6.f },
    };
    for (int idx = threadIdx.x; idx < NUM_INTERVALS * NUM_CH; idx += blockDim.x) {
        const int j = idx >> 6;          // 0..10
        const int c = idx & 63;
        float a0 = 0.f, a1 = 0.f, a2 = 0.f, a3 = 0.f;
#pragma unroll
        for (int k = 0; k < 4; k++) {
            const int i = j - 3 + k;
            if (i >= 0 && i < NUM_CP) {
                const float p = __ldg(&cp[c * NUM_CP + i]);
                a0 = fmaf(p, M[k][0], a0);
                a1 = fmaf(p, M[k][1], a1);
                a2 = fmaf(p, M[k][2], a2);
                a3 = fmaf(p, M[k][3], a3);
            }
        }
        const int slot = ((c & 3) << 4) | (c >> 2);   // bank-tiling swizzle
        sco[(j << 6) + slot] = make_float4(a0, a1, a2, a3);
    }
    __syncthreads();

    // ---- hot loop: 2 float4s per thread per iteration ----
    // Per-s BYTE offset of (j=0, channel cbase+s), so the per-element
    // address is a single IMAD(j, 1024, base_s).
    const float* sco_f = (const float*)sco;
    const int cbase = (threadIdx.x << 2) & 63;
    const float* base_s[4];
#pragma unroll
    for (int s = 0; s < 4; s++) {
        const int c = cbase + s;
        base_s[s] = sco_f + 4 * (((c & 3) << 4) | (c >> 2));
    }

    const int chunk  = 2 * blockDim.x;                // 512 float4s per block-iter
    const int stride = gridDim.x * chunk;

    for (int base = blockIdx.x * chunk + threadIdx.x; base < nvec; base += stride) {
        const int v0 = base;
        const int v1 = base + (int)blockDim.x;
        const bool has1 = (v1 < nvec);

        float4 xa = x4[v0];
        float4 xb = has1 ? x4[v1] : make_float4(0.f, 0.f, 0.f, 0.f);

        float xin[8] = {xa.x, xa.y, xa.z, xa.w, xb.x, xb.y, xb.z, xb.w};
        float yo[8];
#pragma unroll
        for (int s = 0; s < 8; s++) {
            float xx = fminf(fmaxf(xin[s], -0.99f), 0.99f);
            float u  = fmaf(xx, 5.5f, 5.5f);          // in [0.055, 10.945]
            float m  = fmaf(xx, 5.5f, FBASE + 5.0f);  // = FBASE + floor(u)
            int   j  = __float_as_int(m) & 15;        // proven 0..10
            float t  = u - (m - FBASE);
            const float4 co = *(const float4*)(base_s[s & 3] + (j << 8)); // j*1024 B
            yo[s] = fmaf(fmaf(fmaf(co.w, t, co.z), t, co.y), t, co.x);
        }
        __stcs(&out4[v0], make_float4(yo[0], yo[1], yo[2], yo[3]));
        if (has1)
            __stcs(&out4[v1], make_float4(yo[4], yo[5], yo[6], yo[7]));
    }
}

extern "C" void kernel_launch(void* const* d_in, const int* in_sizes, int n_in,
                              void* d_out, int out_size) {
    const float* x  = (const float*)d_in[0];          // [262144, 64]
    const float* cp = (const float*)d_in[1];          // [64, 8]
    float* out = (float*)d_out;

    const int n = in_sizes[0];                        // B*C elements
    const int nvec = n >> 2;                          // float4 count

    const int threads = 256;
    const int blocks = 1184;                          // 148 SMs x 8 CTAs
    kan_fused_kernel<<<blocks, threads>>>((const float4*)x, cp,
                                          (float4*)out, nvec);
}